// round 6
// baseline (speedup 1.0000x reference)
#include <cuda_runtime.h>

#define NC    10
#define TPB   256
#define NBLK  1036   // 148 SMs x 7 CTAs -> exactly one wave at 36 regs

// slots 0..9: per-class sqerr sums; slots 10..19: per-class counts
__device__ float g_partials[2 * NC * NBLK];
__device__ unsigned int g_ticket = 0;

// Branch-free predicated accumulate: ISETP (alu) + @P FADD (fma). No BSSY/BSYNC.
#define PSUM(c)                                                             \
    asm("{.reg .pred p; setp.eq.s32 p, %1, %2; @p add.f32 %0, %0, %3;}"     \
        : "+f"(sum[c]) : "r"(cls), "n"(c), "f"(sq))

__device__ __forceinline__ void proc_elem(float ov, float tv, int mv,
                                          float (&sum)[NC],
                                          unsigned long long& pk0,
                                          unsigned long long& pk1)
{
    float d  = ov - tv;
    float sq = d * d;
    int cls  = (int)tv;                 // targets are exact small ints
    cls = (mv == 1) ? cls : NC;         // invalid -> dummy class 10
    PSUM(0); PSUM(1); PSUM(2); PSUM(3); PSUM(4);
    PSUM(5); PSUM(6); PSUM(7); PSUM(8); PSUM(9);
    // 12-bit packed counts: classes 0-4 in pk0, 5-9 in pk1;
    // dummy cls 10 -> pk1 bits 60.. (carries fall off the top, harmless).
    bool hi  = (cls >= 5);
    int slot = hi ? cls - 5 : cls;
    unsigned long long inc = 1ull << (slot * 12);
    if (hi) pk1 += inc; else pk0 += inc;
}

__global__ __launch_bounds__(TPB, 7) void myloss2_fused_kernel(
    const float* __restrict__ o,
    const float* __restrict__ t,
    const int*   __restrict__ m,
    float* __restrict__ out,
    int n)
{
    float sum[NC];
#pragma unroll
    for (int c = 0; c < NC; c++) sum[c] = 0.f;
    unsigned long long pk0 = 0, pk1 = 0;

    const int nvec = n >> 2;
    const float4* __restrict__ o4 = (const float4*)o;
    const float4* __restrict__ t4 = (const float4*)t;
    const int4*   __restrict__ m4 = (const int4*)m;

    const int nthreads  = NBLK * TPB;
    const int gid       = blockIdx.x * TPB + threadIdx.x;
    const int full_iters = nvec / nthreads;   // guard-free uniform portion

    int i = gid;
#pragma unroll 2
    for (int r = 0; r < full_iters; r++, i += nthreads) {
        float4 ov = o4[i];
        float4 tv = t4[i];
        int4   mv = m4[i];
        proc_elem(ov.x, tv.x, mv.x, sum, pk0, pk1);
        proc_elem(ov.y, tv.y, mv.y, sum, pk0, pk1);
        proc_elem(ov.z, tv.z, mv.z, sum, pk0, pk1);
        proc_elem(ov.w, tv.w, mv.w, sum, pk0, pk1);
    }
    // remainder vec4s (at most one extra per thread)
    for (; i < nvec; i += nthreads) {
        float4 ov = o4[i];
        float4 tv = t4[i];
        int4   mv = m4[i];
        proc_elem(ov.x, tv.x, mv.x, sum, pk0, pk1);
        proc_elem(ov.y, tv.y, mv.y, sum, pk0, pk1);
        proc_elem(ov.z, tv.z, mv.z, sum, pk0, pk1);
        proc_elem(ov.w, tv.w, mv.w, sum, pk0, pk1);
    }
    // scalar tail (n % 4 != 0 -- not hit for this shape, kept for safety)
    if (blockIdx.x == 0 && threadIdx.x == 0) {
        for (int k = (nvec << 2); k < n; k++)
            proc_elem(o[k], t[k], m[k], sum, pk0, pk1);
    }

    // unpack counts
    float cnt[NC];
#pragma unroll
    for (int c = 0; c < 5; c++) {
        cnt[c]     = (float)((unsigned)(pk0 >> (c * 12)) & 0xFFFu);
        cnt[c + 5] = (float)((unsigned)(pk1 >> (c * 12)) & 0xFFFu);
    }

    // warp reduce 20 values
    const unsigned full = 0xffffffffu;
#pragma unroll
    for (int c = 0; c < NC; c++) {
#pragma unroll
        for (int off = 16; off; off >>= 1) {
            sum[c] += __shfl_down_sync(full, sum[c], off);
            cnt[c] += __shfl_down_sync(full, cnt[c], off);
        }
    }

    __shared__ float sh[2 * NC][TPB / 32];
    __shared__ float red[2 * NC];
    __shared__ unsigned int s_is_last;
    const int wid = threadIdx.x >> 5;
    const int lid = threadIdx.x & 31;
    if (lid == 0) {
#pragma unroll
        for (int c = 0; c < NC; c++) {
            sh[c][wid]      = sum[c];
            sh[NC + c][wid] = cnt[c];
        }
    }
    __syncthreads();

    if (threadIdx.x < 2 * NC) {
        float a = 0.f;
#pragma unroll
        for (int w = 0; w < TPB / 32; w++) a += sh[threadIdx.x][w];
        g_partials[threadIdx.x * NBLK + blockIdx.x] = a;  // deterministic write
    }

    // ---- last-block-done fused finalize ----
    __threadfence();
    if (threadIdx.x == 0) {
        unsigned int tk = atomicAdd(&g_ticket, 1u);
        s_is_last = (tk == (unsigned)(gridDim.x - 1)) ? 1u : 0u;
    }
    __syncthreads();
    if (!s_is_last) return;

    for (int slot = wid; slot < 2 * NC; slot += TPB / 32) {
        float a = 0.f;
        for (int b = lid; b < NBLK; b += 32)
            a += g_partials[slot * NBLK + b];
#pragma unroll
        for (int off = 16; off; off >>= 1)
            a += __shfl_down_sync(full, a, off);
        if (lid == 0) red[slot] = a;
    }
    __syncthreads();

    if (threadIdx.x == 0) {
        float loss = 0.f;
#pragma unroll
        for (int c = 0; c < NC; c++) {
            float s  = red[c];
            float nn = red[NC + c];
            float le = (nn > 0.f) ? s / fmaxf(nn, 1.0f) : 0.0f;
            out[1 + c]  = le;   // loss_each
            out[11 + c] = nn;   // class_n
            loss += 0.1f * le;
        }
        out[0] = loss;
        g_ticket = 0;           // reset for next graph replay
    }
}

extern "C" void kernel_launch(void* const* d_in, const int* in_sizes, int n_in,
                              void* d_out, int out_size)
{
    const float* o = (const float*)d_in[0];
    const float* t = (const float*)d_in[1];
    const int*   m = (const int*)d_in[2];
    float* out = (float*)d_out;
    int n = in_sizes[0];

    myloss2_fused_kernel<<<NBLK, TPB>>>(o, t, m, out, n);
}

// round 7
// speedup vs baseline: 1.5514x; 1.5514x over previous
#include <cuda_runtime.h>

#define NC    10
#define TPB   256
#define NBLK  592   // 148 SMs x 4 CTAs -> exactly one wave at <=52 regs

// slots 0..9: per-class sqerr sums; slots 10..19: per-class counts
__device__ float g_partials[2 * NC * NBLK];
__device__ unsigned int g_ticket = 0;

// One ISETP (alu) + two predicated FFMA-imm (fma pipe, rt=1).
// sum[c] += sq; cnt[c] += 1.0f, both guarded by (cls == c). No branches.
#define PACC(c)                                                              \
    asm("{.reg .pred p;\n\t"                                                 \
        "setp.eq.s32 p, %2, " #c ";\n\t"                                     \
        "@p fma.rn.f32 %0, %3, 0f3F800000, %0;\n\t"                          \
        "@p fma.rn.f32 %1, %4, 0f3F800000, %1;}"                             \
        : "+f"(sum[c]), "+f"(cnt[c]) : "r"(cls), "f"(sq), "f"(onef))

__device__ __forceinline__ void proc_elem(float ov, float tv, int mv,
                                          float (&sum)[NC], float (&cnt)[NC],
                                          float onef)
{
    float d  = ov - tv;
    float sq = d * d;
    int cls  = (int)tv;                 // targets are exact small ints
    cls = (mv == 1) ? cls : NC;         // invalid -> dummy class 10 (never matches)
    PACC(0); PACC(1); PACC(2); PACC(3); PACC(4);
    PACC(5); PACC(6); PACC(7); PACC(8); PACC(9);
}

__global__ __launch_bounds__(TPB, 4) void myloss2_fused_kernel(
    const float* __restrict__ o,
    const float* __restrict__ t,
    const int*   __restrict__ m,
    float* __restrict__ out,
    int n)
{
    float sum[NC], cnt[NC];
#pragma unroll
    for (int c = 0; c < NC; c++) { sum[c] = 0.f; cnt[c] = 0.f; }
    const float onef = 1.0f;

    const int nvec = n >> 2;
    const float4* __restrict__ o4 = (const float4*)o;
    const float4* __restrict__ t4 = (const float4*)t;
    const int4*   __restrict__ m4 = (const int4*)m;

    const int nthreads   = NBLK * TPB;
    const int gid        = blockIdx.x * TPB + threadIdx.x;
    const int full_iters = nvec / nthreads;   // guard-free uniform portion

    int i = gid;
#pragma unroll 2
    for (int r = 0; r < full_iters; r++, i += nthreads) {
        float4 ov = o4[i];
        float4 tv = t4[i];
        int4   mv = m4[i];
        proc_elem(ov.x, tv.x, mv.x, sum, cnt, onef);
        proc_elem(ov.y, tv.y, mv.y, sum, cnt, onef);
        proc_elem(ov.z, tv.z, mv.z, sum, cnt, onef);
        proc_elem(ov.w, tv.w, mv.w, sum, cnt, onef);
    }
    // remainder vec4s (at most one extra per thread)
    for (; i < nvec; i += nthreads) {
        float4 ov = o4[i];
        float4 tv = t4[i];
        int4   mv = m4[i];
        proc_elem(ov.x, tv.x, mv.x, sum, cnt, onef);
        proc_elem(ov.y, tv.y, mv.y, sum, cnt, onef);
        proc_elem(ov.z, tv.z, mv.z, sum, cnt, onef);
        proc_elem(ov.w, tv.w, mv.w, sum, cnt, onef);
    }
    // scalar tail (n % 4 != 0 -- not hit for this shape, kept for safety)
    if (blockIdx.x == 0 && threadIdx.x == 0) {
        for (int k = (nvec << 2); k < n; k++)
            proc_elem(o[k], t[k], m[k], sum, cnt, onef);
    }

    // warp reduce 20 values
    const unsigned full = 0xffffffffu;
#pragma unroll
    for (int c = 0; c < NC; c++) {
#pragma unroll
        for (int off = 16; off; off >>= 1) {
            sum[c] += __shfl_down_sync(full, sum[c], off);
            cnt[c] += __shfl_down_sync(full, cnt[c], off);
        }
    }

    __shared__ float sh[2 * NC][TPB / 32];
    __shared__ float red[2 * NC];
    __shared__ unsigned int s_is_last;
    const int wid = threadIdx.x >> 5;
    const int lid = threadIdx.x & 31;
    if (lid == 0) {
#pragma unroll
        for (int c = 0; c < NC; c++) {
            sh[c][wid]      = sum[c];
            sh[NC + c][wid] = cnt[c];
        }
    }
    __syncthreads();

    if (threadIdx.x < 2 * NC) {
        float a = 0.f;
#pragma unroll
        for (int w = 0; w < TPB / 32; w++) a += sh[threadIdx.x][w];
        g_partials[threadIdx.x * NBLK + blockIdx.x] = a;  // deterministic write
    }

    // ---- last-block-done fused finalize ----
    __threadfence();
    if (threadIdx.x == 0) {
        unsigned int tk = atomicAdd(&g_ticket, 1u);
        s_is_last = (tk == (unsigned)(gridDim.x - 1)) ? 1u : 0u;
    }
    __syncthreads();
    if (!s_is_last) return;

    for (int slot = wid; slot < 2 * NC; slot += TPB / 32) {
        float a = 0.f;
        for (int b = lid; b < NBLK; b += 32)
            a += g_partials[slot * NBLK + b];
#pragma unroll
        for (int off = 16; off; off >>= 1)
            a += __shfl_down_sync(full, a, off);
        if (lid == 0) red[slot] = a;
    }
    __syncthreads();

    if (threadIdx.x == 0) {
        float loss = 0.f;
#pragma unroll
        for (int c = 0; c < NC; c++) {
            float s  = red[c];
            float nn = red[NC + c];
            float le = (nn > 0.f) ? s / fmaxf(nn, 1.0f) : 0.0f;
            out[1 + c]  = le;   // loss_each
            out[11 + c] = nn;   // class_n
            loss += 0.1f * le;
        }
        out[0] = loss;
        g_ticket = 0;           // reset for next graph replay
    }
}

extern "C" void kernel_launch(void* const* d_in, const int* in_sizes, int n_in,
                              void* d_out, int out_size)
{
    const float* o = (const float*)d_in[0];
    const float* t = (const float*)d_in[1];
    const int*   m = (const int*)d_in[2];
    float* out = (float*)d_out;
    int n = in_sizes[0];

    myloss2_fused_kernel<<<NBLK, TPB>>>(o, t, m, out, n);
}